// round 1
// baseline (speedup 1.0000x reference)
#include <cuda_runtime.h>
#include <math.h>

#define NMAX 50000
#define EMAX 800000
#define DIM 128
#define KF 162   // 128 emb + 34 fixed

// ---------------- scratch (device globals; no allocation allowed) ----------------
__device__ float g_f[(size_t)NMAX * KF];     // concat(emb[idx], x_fixed)
__device__ float g_h[(size_t)NMAX * DIM];    // hidden (ping)
__device__ float g_t[(size_t)NMAX * DIM];    // h @ W.T (pong)
__device__ float g_dinv[NMAX];
__device__ int   g_cnt[NMAX];
__device__ int   g_rowstart[NMAX + 1];
__device__ int   g_cursor[NMAX];
__device__ int   g_col[EMAX];
__device__ int   g_is64;

// ---------------- edge dtype detection ----------------
__global__ void detect_kernel(const int* __restrict__ w) {
    if (threadIdx.x == 0 && blockIdx.x == 0) {
        int any = 0;
        for (int i = 1; i < 256; i += 2) any |= w[i];
        g_is64 = (any == 0) ? 1 : 0;   // int64 little-endian: high words all zero
    }
}

__device__ __forceinline__ int load_edge(const void* edge, size_t pos, int is64) {
    if (is64) return (int)((const long long*)edge)[pos];
    return ((const int*)edge)[pos];
}

// ---------------- front-end: argmax + embedding + concat ----------------
__global__ void prep_kernel(const float* __restrict__ x, const float* __restrict__ emb, int n) {
    int gw   = (blockIdx.x * blockDim.x + threadIdx.x) >> 5;
    int lane = threadIdx.x & 31;
    if (gw >= n) return;
    const float* xi = x + (size_t)gw * 78;
    float best = -1e38f; int bi = 1 << 30;
    for (int k = lane; k < 44; k += 32) {
        float v = xi[k];
        if (v > best || (v == best && k < bi)) { best = v; bi = k; }
    }
    for (int off = 16; off; off >>= 1) {
        float ov = __shfl_xor_sync(0xffffffffu, best, off);
        int   oi = __shfl_xor_sync(0xffffffffu, bi, off);
        if (ov > best || (ov == best && oi < bi)) { best = ov; bi = oi; }
    }
    float* fi = g_f + (size_t)gw * KF;
    const float* er = emb + (size_t)bi * DIM;
    for (int k = lane; k < DIM; k += 32) fi[k] = er[k];
    for (int k = lane; k < 34;  k += 32) fi[DIM + k] = xi[44 + k];
}

// ---------------- CSR build ----------------
__global__ void zero_cnt_kernel(int n) {
    int i = blockIdx.x * blockDim.x + threadIdx.x;
    if (i < n) g_cnt[i] = 0;
}

__global__ void count_kernel(const void* __restrict__ edge, int e) {
    int i = blockIdx.x * blockDim.x + threadIdx.x;
    if (i >= e) return;
    int d = load_edge(edge, (size_t)e + i, g_is64);
    atomicAdd(&g_cnt[d], 1);
}

__global__ void scan_kernel(int n) {
    __shared__ int wsum[32];
    __shared__ int carry;
    int tid = threadIdx.x, lane = tid & 31, wid = tid >> 5;
    if (tid == 0) carry = 0;
    __syncthreads();
    for (int base = 0; base < n; base += 1024) {
        int i = base + tid;
        int v = (i < n) ? g_cnt[i] : 0;
        int x = v;
        #pragma unroll
        for (int off = 1; off < 32; off <<= 1) {
            int t = __shfl_up_sync(0xffffffffu, x, off);
            if (lane >= off) x += t;
        }
        if (lane == 31) wsum[wid] = x;
        __syncthreads();
        if (wid == 0) {
            int y = wsum[lane];
            #pragma unroll
            for (int off = 1; off < 32; off <<= 1) {
                int t = __shfl_up_sync(0xffffffffu, y, off);
                if (lane >= off) y += t;
            }
            wsum[lane] = y;
        }
        __syncthreads();
        int incl  = x + (wid ? wsum[wid - 1] : 0);
        int start = carry + incl - v;
        if (i < n) {
            g_rowstart[i] = start;
            g_cursor[i]   = start;
            g_dinv[i]     = rsqrtf((float)(v + 1));   // +1 self loop
        }
        int total = wsum[31];
        __syncthreads();
        if (tid == 0) carry += total;
        __syncthreads();
    }
    if (threadIdx.x == 0) g_rowstart[n] = carry;
}

__global__ void fill_kernel(const void* __restrict__ edge, int e) {
    int i = blockIdx.x * blockDim.x + threadIdx.x;
    if (i >= e) return;
    int is64 = g_is64;
    int s = load_edge(edge, (size_t)i, is64);
    int d = load_edge(edge, (size_t)e + i, is64);
    int p = atomicAdd(&g_cursor[d], 1);
    g_col[p] = s;
}

// ---------------- register-tiled fp32 GEMM: C[n,128] = act(A[n,K] @ W[128,K]^T + b) ----------------
// 128 threads/block, block tile = 64 nodes x 128 outputs, 8x8 per thread.
#define WPITCH 132   // padded k-major pitch for W in shared

template<int K, bool RELU_BIAS>
__global__ void __launch_bounds__(128) gemm_kernel(
    const float* __restrict__ A, const float* __restrict__ W,
    const float* __restrict__ bias, float* __restrict__ C, int n)
{
    extern __shared__ float sm[];
    float* Ws = sm;               // [K][WPITCH]
    float* Fs = sm + K * WPITCH;  // [64][K]
    const int tid  = threadIdx.x;
    const int base = blockIdx.x * 64;

    // Load W (k-major transpose in smem)
    for (int idx = tid; idx < 128 * K; idx += 128) {
        int o = idx / K, k = idx - o * K;
        Ws[k * WPITCH + o] = W[idx];
    }
    // Load F (node-major, coalesced both sides)
    for (int idx = tid; idx < 64 * K; idx += 128) {
        int node = idx / K, k = idx - node * K;
        int gi = base + node;
        Fs[idx] = (gi < n) ? A[(size_t)gi * K + k] : 0.f;
    }
    __syncthreads();

    const int tx = tid & 15;   // output group: outs tx*8..tx*8+7
    const int ty = tid >> 4;   // node group:  nodes ty*8..ty*8+7

    float acc[8][8];
    #pragma unroll
    for (int a = 0; a < 8; a++)
        #pragma unroll
        for (int b = 0; b < 8; b++) acc[a][b] = 0.f;

    const float* frow = Fs + (ty * 8) * K;
    for (int k = 0; k < K; k++) {
        float4 wa = *(const float4*)&Ws[k * WPITCH + tx * 8];
        float4 wb = *(const float4*)&Ws[k * WPITCH + tx * 8 + 4];
        float w[8] = {wa.x, wa.y, wa.z, wa.w, wb.x, wb.y, wb.z, wb.w};
        float f[8];
        #pragma unroll
        for (int jn = 0; jn < 8; jn++) f[jn] = frow[jn * K + k];
        #pragma unroll
        for (int jn = 0; jn < 8; jn++)
            #pragma unroll
            for (int jo = 0; jo < 8; jo++)
                acc[jn][jo] = fmaf(f[jn], w[jo], acc[jn][jo]);
    }

    float bv[8];
    if (RELU_BIAS) {
        #pragma unroll
        for (int j = 0; j < 8; j++) bv[j] = bias[tx * 8 + j];
    }
    #pragma unroll
    for (int jn = 0; jn < 8; jn++) {
        int gi = base + ty * 8 + jn;
        if (gi < n) {
            float v[8];
            #pragma unroll
            for (int jo = 0; jo < 8; jo++) {
                float r = acc[jn][jo];
                if (RELU_BIAS) r = fmaxf(r + bv[jo], 0.f);
                v[jo] = r;
            }
            float* cp = C + (size_t)gi * 128 + tx * 8;
            *(float4*)cp       = make_float4(v[0], v[1], v[2], v[3]);
            *(float4*)(cp + 4) = make_float4(v[4], v[5], v[6], v[7]);
        }
    }
}

// ---------------- CSR gather aggregation (no atomics): out = relu(dinv_i*sum + dinv_i^2*t_i + b) ----------------
__global__ void agg_kernel(const float* __restrict__ t, const float* __restrict__ bias,
                           float* __restrict__ out, int n)
{
    int gw   = (blockIdx.x * blockDim.x + threadIdx.x) >> 5;
    int lane = threadIdx.x & 31;
    if (gw >= n) return;
    int r0 = g_rowstart[gw], r1 = g_rowstart[gw + 1];
    const float4* t4 = (const float4*)t;

    float4 a0 = make_float4(0.f, 0.f, 0.f, 0.f);
    float4 a1 = make_float4(0.f, 0.f, 0.f, 0.f);
    int e = r0;
    for (; e + 1 < r1; e += 2) {
        int s0 = g_col[e], s1 = g_col[e + 1];
        float w0 = g_dinv[s0], w1 = g_dinv[s1];
        float4 v0 = t4[(size_t)s0 * 32 + lane];
        float4 v1 = t4[(size_t)s1 * 32 + lane];
        a0.x = fmaf(w0, v0.x, a0.x); a0.y = fmaf(w0, v0.y, a0.y);
        a0.z = fmaf(w0, v0.z, a0.z); a0.w = fmaf(w0, v0.w, a0.w);
        a1.x = fmaf(w1, v1.x, a1.x); a1.y = fmaf(w1, v1.y, a1.y);
        a1.z = fmaf(w1, v1.z, a1.z); a1.w = fmaf(w1, v1.w, a1.w);
    }
    if (e < r1) {
        int s = g_col[e];
        float w = g_dinv[s];
        float4 v = t4[(size_t)s * 32 + lane];
        a0.x = fmaf(w, v.x, a0.x); a0.y = fmaf(w, v.y, a0.y);
        a0.z = fmaf(w, v.z, a0.z); a0.w = fmaf(w, v.w, a0.w);
    }
    float di  = g_dinv[gw];
    float di2 = di * di;
    float4 sv = t4[(size_t)gw * 32 + lane];
    float4 b4 = ((const float4*)bias)[lane];
    float4 o;
    o.x = fmaxf(di * (a0.x + a1.x) + di2 * sv.x + b4.x, 0.f);
    o.y = fmaxf(di * (a0.y + a1.y) + di2 * sv.y + b4.y, 0.f);
    o.z = fmaxf(di * (a0.z + a1.z) + di2 * sv.z + b4.z, 0.f);
    o.w = fmaxf(di * (a0.w + a1.w) + di2 * sv.w + b4.w, 0.f);
    ((float4*)out)[(size_t)gw * 32 + lane] = o;
}

// ---------------- launch ----------------
extern "C" void kernel_launch(void* const* d_in, const int* in_sizes, int n_in,
                              void* d_out, int out_size)
{
    const float* x     = (const float*)d_in[0];
    const void*  edge  = d_in[1];                 // int32 or int64, detected on device
    const float* emb   = (const float*)d_in[3];
    const float* lin_W = (const float*)d_in[4];
    const float* lin_b = (const float*)d_in[5];
    const float* g1W   = (const float*)d_in[6];
    const float* g1b   = (const float*)d_in[7];
    const float* g2W   = (const float*)d_in[8];
    const float* g2b   = (const float*)d_in[9];

    int n = in_sizes[0] / 78;
    int e = in_sizes[1] / 2;
    float* out = (float*)d_out;

    float *f_, *h_, *t_;
    cudaGetSymbolAddress((void**)&f_, g_f);
    cudaGetSymbolAddress((void**)&h_, g_h);
    cudaGetSymbolAddress((void**)&t_, g_t);

    const int SMEM162 = (KF  * WPITCH + 64 * KF ) * 4;   // 127008
    const int SMEM128 = (DIM * WPITCH + 64 * DIM) * 4;   // 100352
    cudaFuncSetAttribute(gemm_kernel<KF,  true >, cudaFuncAttributeMaxDynamicSharedMemorySize, SMEM162);
    cudaFuncSetAttribute(gemm_kernel<DIM, false>, cudaFuncAttributeMaxDynamicSharedMemorySize, SMEM128);

    int ngrid_warp = (n + 7) / 8;         // 256 threads = 8 warps/block
    int egrid      = (e + 255) / 256;
    int gemm_grid  = (n + 63) / 64;

    detect_kernel<<<1, 32>>>((const int*)edge);
    prep_kernel<<<ngrid_warp, 256>>>(x, emb, n);
    zero_cnt_kernel<<<(n + 255) / 256, 256>>>(n);
    count_kernel<<<egrid, 256>>>(edge, e);
    scan_kernel<<<1, 1024>>>(n);
    fill_kernel<<<egrid, 256>>>(edge, e);

    // h = relu(F @ lin_W^T + lin_b)
    gemm_kernel<KF, true ><<<gemm_grid, 128, SMEM162>>>(f_, lin_W, lin_b, h_, n);
    // layer 1
    gemm_kernel<DIM, false><<<gemm_grid, 128, SMEM128>>>(h_, g1W, nullptr, t_, n);
    agg_kernel<<<ngrid_warp, 256>>>(t_, g1b, h_, n);
    // layer 2
    gemm_kernel<DIM, false><<<gemm_grid, 128, SMEM128>>>(h_, g2W, nullptr, t_, n);
    agg_kernel<<<ngrid_warp, 256>>>(t_, g2b, out, n);
}